// round 14
// baseline (speedup 1.0000x reference)
#include <cuda_runtime.h>
#include <cuda_fp16.h>
#include <cstdint>

// Problem dims (fixed by the dataset)
#define D_DIM 4096
#define H_DIM 11008
#define T_MAX 8192

__device__ __constant__ float c_nf4[16] = {
    -1.0f, -0.6961928009986877f, -0.5250730514526367f, -0.39491748809814453f,
    -0.28444138169288635f, -0.18477343022823334f, -0.09105003625154495f, 0.0f,
    0.07958029955625534f, 0.16093020141124725f, 0.24611230194568634f,
    0.33791524171829224f, 0.44070982933044434f, 0.5626170039176941f,
    0.7229568362236023f, 1.0f};

// Scratch (static __device__ arrays: allocation-guard safe)
__device__ __align__(256) __half g_w1[(size_t)H_DIM * D_DIM];
__device__ __align__(256) __half g_w2[(size_t)H_DIM * D_DIM];
__device__ __align__(256) __half g_w3[(size_t)D_DIM * H_DIM];
__device__ __align__(256) __half g_x [(size_t)T_MAX * D_DIM];
__device__ __align__(256) __half g_h [(size_t)T_MAX * H_DIM];

#define NW16 ((H_DIM * D_DIM) / 16)  // 2,818,048 dequant items per weight

// ---------------------------------------------------------------------------
// Dequant core: 16 codes (4 x int4) -> 16 fp16, one scaler per 64-elem block.
// ---------------------------------------------------------------------------
__device__ __forceinline__ void dq16(const int* __restrict__ codes,
                                     const float* __restrict__ scalers,
                                     __half* __restrict__ out, int i) {
    const int4* cp = (const int4*)codes + (size_t)i * 4;
    float s = __ldg(&scalers[i >> 2]);
    int4 c0 = cp[0], c1 = cp[1], c2 = cp[2], c3 = cp[3];
    uint4 o0, o1;
    __half2* h = (__half2*)&o0;
    h[0] = __floats2half2_rn(c_nf4[c0.x & 15] * s, c_nf4[c0.y & 15] * s);
    h[1] = __floats2half2_rn(c_nf4[c0.z & 15] * s, c_nf4[c0.w & 15] * s);
    h[2] = __floats2half2_rn(c_nf4[c1.x & 15] * s, c_nf4[c1.y & 15] * s);
    h[3] = __floats2half2_rn(c_nf4[c1.z & 15] * s, c_nf4[c1.w & 15] * s);
    __half2* g = (__half2*)&o1;
    g[0] = __floats2half2_rn(c_nf4[c2.x & 15] * s, c_nf4[c2.y & 15] * s);
    g[1] = __floats2half2_rn(c_nf4[c2.z & 15] * s, c_nf4[c2.w & 15] * s);
    g[2] = __floats2half2_rn(c_nf4[c3.x & 15] * s, c_nf4[c3.y & 15] * s);
    g[3] = __floats2half2_rn(c_nf4[c3.z & 15] * s, c_nf4[c3.w & 15] * s);
    uint4* op = (uint4*)out + (size_t)i * 2;
    op[0] = o0;
    op[1] = o1;
}

// ---------------------------------------------------------------------------
// Elementwise prep — separate kernels (round-12 proven fast versions).
// ---------------------------------------------------------------------------
__global__ void dequant_nf4_kernel(const int* __restrict__ codes,
                                   const float* __restrict__ scalers,
                                   __half* __restrict__ out, int n16) {
    int i = blockIdx.x * blockDim.x + threadIdx.x;
    if (i >= n16) return;
    dq16(codes, scalers, out, i);
}

__global__ void f32_to_f16_kernel(const float* __restrict__ in,
                                  __half* __restrict__ out, int n8) {
    int i = blockIdx.x * blockDim.x + threadIdx.x;
    if (i >= n8) return;
    const float4* ip = (const float4*)in + (size_t)i * 2;
    float4 v0 = ip[0], v1 = ip[1];
    uint4 o;
    __half2* h = (__half2*)&o;
    h[0] = __floats2half2_rn(v0.x, v0.y);
    h[1] = __floats2half2_rn(v0.z, v0.w);
    h[2] = __floats2half2_rn(v1.x, v1.y);
    h[3] = __floats2half2_rn(v1.z, v1.w);
    ((uint4*)out)[i] = o;
}

// ---------------------------------------------------------------------------
// GEMM, proven mainloop (CTA 128 M x 128 B-rows x 64 K, 4 warps 2x2, warp
// tile 64x64, 2 CTAs/SM, 3-stage ring, cross-stage fragment prefetch,
// L2-aware rasterization with RASTER_G M-tile groups).
//
// FUSED=1: B rows 0..63 = w1 tile, rows 64..127 = w2 tile (same 64 cols);
//          epilogue h = half(silu(acc_w1)*acc_w2). Grid has one EXTRA y-row:
//          CTAs with linear >= 172*64 grid-stride the w3 NF4 dequant
//          (tail-wave overlap; GEMM DRAM is ~4% so bandwidth is free).
// FUSED=0: plain C[M,N] = A@B^T, fp32 out (down-projection).
// ---------------------------------------------------------------------------
#define BM 128
#define BK 64
#define STG_A (BM * BK * 2)              // 16 KB
#define STG_BYTES ((BM + 128) * BK * 2)  // 32 KB
#define NSTAGE 3
#define SMEM_TOTAL (NSTAGE * STG_BYTES)  // 96 KB per CTA
#define RASTER_G 16
#define FUSED_TILES (172 * 64)           // 11008 MMA CTAs in the fused grid

__device__ __forceinline__ void cp_async16(uint32_t dst, const void* src) {
    asm volatile("cp.async.cg.shared.global [%0], [%1], 16;\n" ::"r"(dst), "l"(src));
}

template <int FUSED>
__global__ void __launch_bounds__(128, 2) gemm_kernel(
    const __half* __restrict__ A, const __half* __restrict__ B1,
    const __half* __restrict__ B2, void* __restrict__ Cout,
    const int* __restrict__ w3c, const float* __restrict__ w3s,
    int M, int Nout, int K) {
    extern __shared__ __align__(128) char smem_raw[];
    uint32_t smem_base = (uint32_t)__cvta_generic_to_shared(smem_raw);

    int tid  = threadIdx.x;
    int lane = tid & 31;
    int warp = tid >> 5;
    int wrow = warp >> 1;  // 0..1 -> 64 rows each
    int wcol = warp & 1;   // 0..1

    int tiles_n = gridDim.x;
    int linear = blockIdx.y * tiles_n + blockIdx.x;

    if (FUSED) {
        // Tail CTAs (last-launched): w3 dequant, overlapped with GEMM tail.
        if (linear >= FUSED_TILES) {
            int t = (linear - FUSED_TILES) * 128 + tid;  // 0..22015
            for (int i = t; i < NW16; i += 172 * 128) dq16(w3c, w3s, g_w3, i);
            return;
        }
    }

    // ---- L2-aware rasterization (M-tiles fastest within groups of RASTER_G)
    int gsz = RASTER_G * tiles_n;
    int grp = linear / gsz;
    int rem = linear - grp * gsz;
    int m_idx = grp * RASTER_G + (rem % RASTER_G);
    int n_idx = rem / RASTER_G;

    long bm0 = (long)m_idx * BM;
    long bn0 = (long)n_idx * (FUSED ? 64 : 128);

    const __half* Ablk  = A + bm0 * K;
    const __half* B1blk = B1 + bn0 * K;
    const __half* B2blk = FUSED ? (B2 + bn0 * K) : nullptr;

    int KT = K / BK;

    auto load_stage = [&](int kt, int s) {
        uint32_t sa = smem_base + s * STG_BYTES;
        uint32_t sbb = sa + STG_A;
        long koff = (long)kt * BK;
#pragma unroll
        for (int i = 0; i < 8; i++) {
            int e = i * 128 + tid;
            int row = e >> 3;
            int chunk = e & 7;
            uint32_t dst = sa + row * 128 + ((chunk * 16) ^ ((row & 7) * 16));
            cp_async16(dst, Ablk + (long)row * K + koff + chunk * 8);
        }
#pragma unroll
        for (int i = 0; i < 8; i++) {
            int e = i * 128 + tid;
            int row = e >> 3;
            int chunk = e & 7;
            uint32_t dst = sbb + row * 128 + ((chunk * 16) ^ ((row & 7) * 16));
            const __half* src;
            if (FUSED)
                src = (row < 64) ? (B1blk + (long)row * K + koff + chunk * 8)
                                 : (B2blk + (long)(row - 64) * K + koff + chunk * 8);
            else
                src = B1blk + (long)row * K + koff + chunk * 8;
            cp_async16(dst, src);
        }
        asm volatile("cp.async.commit_group;\n");
    };

    float acc[4][8][4];
#pragma unroll
    for (int mt = 0; mt < 4; mt++)
#pragma unroll
        for (int nt = 0; nt < 8; nt++)
#pragma unroll
            for (int r = 0; r < 4; r++) acc[mt][nt][r] = 0.f;

    // ---- Hoisted ldmatrix addressing (XOR field decomposition) ----
    const int a_r  = lane & 15;
    const int a_ch = (lane >> 4) * 16;
    const int swzA = (a_r & 7) * 16;
    const uint32_t qA = (uint32_t)(swzA & 96);
    uint32_t aBase[4];
#pragma unroll
    for (int mt = 0; mt < 4; mt++)
        aBase[mt] = (uint32_t)((wrow * 64 + mt * 16 + a_r) * 128 +
                               (a_ch ^ (swzA & 16)));
    const int b_r  = ((lane >> 4) << 3) + (lane & 7);
    const int b_ch = ((lane >> 3) & 1) * 16;
    const int swzB = (lane & 7) * 16;
    const uint32_t qB = (uint32_t)(swzB & 96);
    uint32_t bBase[4];
#pragma unroll
    for (int p = 0; p < 4; p++) {
        int brow;
        if (FUSED)
            brow = (p < 2) ? (wcol * 32 + p * 16 + b_r)
                           : (64 + wcol * 32 + (p - 2) * 16 + b_r);
        else
            brow = wcol * 64 + p * 16 + b_r;
        bBase[p] = (uint32_t)(STG_A + brow * 128 + (b_ch ^ (swzB & 16)));
    }

    uint32_t a_frag[2][4][4];
    uint32_t b_frag[2][8][2];

    auto load_frags = [&](uint32_t st, int k16, int buf) {
        uint32_t xa = ((uint32_t)(k16 * 32)) ^ qA;
        uint32_t xb = ((uint32_t)(k16 * 32)) ^ qB;
#pragma unroll
        for (int mt = 0; mt < 4; mt++) {
            uint32_t addr = st + aBase[mt] + xa;
            asm volatile(
                "ldmatrix.sync.aligned.m8n8.x4.shared.b16 {%0,%1,%2,%3}, [%4];"
                : "=r"(a_frag[buf][mt][0]), "=r"(a_frag[buf][mt][1]),
                  "=r"(a_frag[buf][mt][2]), "=r"(a_frag[buf][mt][3])
                : "r"(addr));
        }
#pragma unroll
        for (int p = 0; p < 4; p++) {
            uint32_t addr = st + bBase[p] + xb;
            asm volatile(
                "ldmatrix.sync.aligned.m8n8.x4.shared.b16 {%0,%1,%2,%3}, [%4];"
                : "=r"(b_frag[buf][2 * p][0]), "=r"(b_frag[buf][2 * p][1]),
                  "=r"(b_frag[buf][2 * p + 1][0]), "=r"(b_frag[buf][2 * p + 1][1])
                : "r"(addr));
        }
    };

    auto do_mmas = [&](int buf) {
#pragma unroll
        for (int mt = 0; mt < 4; mt++)
#pragma unroll
            for (int nt = 0; nt < 8; nt++) {
                asm volatile(
                    "mma.sync.aligned.m16n8k16.row.col.f32.f16.f16.f32 "
                    "{%0,%1,%2,%3}, {%4,%5,%6,%7}, {%8,%9}, {%0,%1,%2,%3};"
                    : "+f"(acc[mt][nt][0]), "+f"(acc[mt][nt][1]),
                      "+f"(acc[mt][nt][2]), "+f"(acc[mt][nt][3])
                    : "r"(a_frag[buf][mt][0]), "r"(a_frag[buf][mt][1]),
                      "r"(a_frag[buf][mt][2]), "r"(a_frag[buf][mt][3]),
                      "r"(b_frag[buf][nt][0]), "r"(b_frag[buf][nt][1]));
            }
    };

    // Prologue
    load_stage(0, 0);
    load_stage(1, 1);
    asm volatile("cp.async.wait_group 1;\n");
    __syncthreads();
    load_frags(smem_base, 0, 0);

    int sc = 0, sl = 2;
    int buf = 0;
    for (int kt = 0; kt < KT; kt++) {
        __syncthreads();

        if (kt + 2 < KT) load_stage(kt + 2, sl);
        else asm volatile("cp.async.commit_group;\n");

        asm volatile("cp.async.wait_group 1;\n");
        __syncthreads();

        uint32_t st = smem_base + sc * STG_BYTES;
        int sn = sc + 1 == NSTAGE ? 0 : sc + 1;
        uint32_t st_next = (kt + 1 < KT) ? smem_base + sn * STG_BYTES : st;
        sc = sn;
        sl = (sl + 1 == NSTAGE) ? 0 : sl + 1;

#pragma unroll
        for (int k16 = 0; k16 < BK / 16; k16++) {
            if (k16 + 1 < BK / 16)
                load_frags(st, k16 + 1, buf ^ 1);
            else
                load_frags(st_next, 0, buf ^ 1);
            do_mmas(buf);
            buf ^= 1;
        }
    }

    // Epilogue
    if (FUSED) {
#pragma unroll
        for (int mt = 0; mt < 4; mt++) {
#pragma unroll
            for (int nt = 0; nt < 4; nt++) {
                long r0 = bm0 + wrow * 64 + mt * 16 + (lane >> 2);
                long c0 = bn0 + wcol * 32 + nt * 8 + (lane & 3) * 2;
                float g0 = acc[mt][nt][0], g1 = acc[mt][nt][1];
                float g2 = acc[mt][nt][2], g3 = acc[mt][nt][3];
                float u0 = acc[mt][nt + 4][0], u1 = acc[mt][nt + 4][1];
                float u2 = acc[mt][nt + 4][2], u3 = acc[mt][nt + 4][3];
                float h0 = g0 / (1.f + __expf(-g0)) * u0;
                float h1 = g1 / (1.f + __expf(-g1)) * u1;
                float h2 = g2 / (1.f + __expf(-g2)) * u2;
                float h3 = g3 / (1.f + __expf(-g3)) * u3;
                __half* C = (__half*)Cout;
                *(__half2*)(C + r0 * Nout + c0)       = __floats2half2_rn(h0, h1);
                *(__half2*)(C + (r0 + 8) * Nout + c0) = __floats2half2_rn(h2, h3);
            }
        }
    } else {
#pragma unroll
        for (int mt = 0; mt < 4; mt++) {
#pragma unroll
            for (int nt = 0; nt < 8; nt++) {
                long r0 = bm0 + wrow * 64 + mt * 16 + (lane >> 2);
                long c0 = bn0 + wcol * 64 + nt * 8 + (lane & 3) * 2;
                float* C = (float*)Cout;
                *(float2*)(C + r0 * Nout + c0) =
                    make_float2(acc[mt][nt][0], acc[mt][nt][1]);
                *(float2*)(C + (r0 + 8) * Nout + c0) =
                    make_float2(acc[mt][nt][2], acc[mt][nt][3]);
            }
        }
    }
}

// ---------------------------------------------------------------------------
// Launch: 5 kernels.
//   idx 0: dq w1      idx 1: dq w2      idx 2: x -> fp16
//   idx 3: fused up-proj (+ tail-CTA w3 dequant)
//   idx 4: down-proj
// ---------------------------------------------------------------------------
extern "C" void kernel_launch(void* const* d_in, const int* in_sizes, int n_in,
                              void* d_out, int out_size) {
    const float* x = (const float*)d_in[0];
    const int* w1c = (const int*)d_in[1];
    const float* w1s = (const float*)d_in[2];
    const int* w2c = (const int*)d_in[3];
    const float* w2s = (const float*)d_in[4];
    const int* w3c = (const int*)d_in[5];
    const float* w3s = (const float*)d_in[6];

    int T = in_sizes[0] / D_DIM;  // 8192

    __half *w1h, *w2h, *w3h, *xh, *hbuf;
    cudaGetSymbolAddress((void**)&w1h, g_w1);
    cudaGetSymbolAddress((void**)&w2h, g_w2);
    cudaGetSymbolAddress((void**)&w3h, g_w3);
    cudaGetSymbolAddress((void**)&xh, g_x);
    cudaGetSymbolAddress((void**)&hbuf, g_h);

    cudaFuncSetAttribute(gemm_kernel<1>, cudaFuncAttributeMaxDynamicSharedMemorySize, SMEM_TOTAL);
    cudaFuncSetAttribute(gemm_kernel<0>, cudaFuncAttributeMaxDynamicSharedMemorySize, SMEM_TOTAL);

    int nX8 = (T * D_DIM) / 8;
    dim3 gf(H_DIM / 64, T / BM + 1);   // 172 x 65 (last y-row = w3 dequant)
    dim3 g2(D_DIM / 128, T / BM);      // 32 x 64

    // idx 0: w1 dequant
    dequant_nf4_kernel<<<(NW16 + 255) / 256, 256>>>(w1c, w1s, w1h, NW16);
    // idx 1: w2 dequant
    dequant_nf4_kernel<<<(NW16 + 255) / 256, 256>>>(w2c, w2s, w2h, NW16);
    // idx 2: x -> fp16
    f32_to_f16_kernel<<<(nX8 + 255) / 256, 256>>>(x, xh, nX8);
    // idx 3: h = silu(x@w1^T) * (x@w2^T)  [fused fp16] + tail w3 dequant
    gemm_kernel<1><<<gf, 128, SMEM_TOTAL>>>(xh, w1h, w2h, hbuf, w3c, w3s,
                                            T, H_DIM, D_DIM);
    // idx 4: out = h @ w3^T (fp32)
    gemm_kernel<0><<<g2, 128, SMEM_TOTAL>>>(hbuf, w3h, nullptr, d_out,
                                            nullptr, nullptr, T, D_DIM, H_DIM);
}

// round 15
// speedup vs baseline: 1.0241x; 1.0241x over previous
#include <cuda_runtime.h>
#include <cuda_fp16.h>
#include <cstdint>

// Problem dims (fixed by the dataset)
#define D_DIM 4096
#define H_DIM 11008
#define T_MAX 8192

__device__ __constant__ float c_nf4[16] = {
    -1.0f, -0.6961928009986877f, -0.5250730514526367f, -0.39491748809814453f,
    -0.28444138169288635f, -0.18477343022823334f, -0.09105003625154495f, 0.0f,
    0.07958029955625534f, 0.16093020141124725f, 0.24611230194568634f,
    0.33791524171829224f, 0.44070982933044434f, 0.5626170039176941f,
    0.7229568362236023f, 1.0f};

// Scratch (static __device__ arrays: allocation-guard safe)
__device__ __align__(256) __half g_w1[(size_t)H_DIM * D_DIM];
__device__ __align__(256) __half g_w2[(size_t)H_DIM * D_DIM];
__device__ __align__(256) __half g_w3[(size_t)D_DIM * H_DIM];
__device__ __align__(256) __half g_x [(size_t)T_MAX * D_DIM];
__device__ __align__(256) __half g_h [(size_t)T_MAX * H_DIM];

// ---------------------------------------------------------------------------
// Elementwise prep — 16 codes/thread (MLP=4), one scaler per thread.
// ---------------------------------------------------------------------------
__global__ void dequant_nf4_kernel(const int* __restrict__ codes,
                                   const float* __restrict__ scalers,
                                   __half* __restrict__ out, int n16) {
    int i = blockIdx.x * blockDim.x + threadIdx.x;
    if (i >= n16) return;
    const int4* cp = (const int4*)codes + (size_t)i * 4;
    float s = __ldg(&scalers[i >> 2]);
    int4 c0 = cp[0], c1 = cp[1], c2 = cp[2], c3 = cp[3];
    uint4 o0, o1;
    __half2* h = (__half2*)&o0;
    h[0] = __floats2half2_rn(c_nf4[c0.x & 15] * s, c_nf4[c0.y & 15] * s);
    h[1] = __floats2half2_rn(c_nf4[c0.z & 15] * s, c_nf4[c0.w & 15] * s);
    h[2] = __floats2half2_rn(c_nf4[c1.x & 15] * s, c_nf4[c1.y & 15] * s);
    h[3] = __floats2half2_rn(c_nf4[c1.z & 15] * s, c_nf4[c1.w & 15] * s);
    __half2* g = (__half2*)&o1;
    g[0] = __floats2half2_rn(c_nf4[c2.x & 15] * s, c_nf4[c2.y & 15] * s);
    g[1] = __floats2half2_rn(c_nf4[c2.z & 15] * s, c_nf4[c2.w & 15] * s);
    g[2] = __floats2half2_rn(c_nf4[c3.x & 15] * s, c_nf4[c3.y & 15] * s);
    g[3] = __floats2half2_rn(c_nf4[c3.z & 15] * s, c_nf4[c3.w & 15] * s);
    uint4* op = (uint4*)out + (size_t)i * 2;
    op[0] = o0;
    op[1] = o1;
}

__global__ void f32_to_f16_kernel(const float* __restrict__ in,
                                  __half* __restrict__ out, int n8) {
    int i = blockIdx.x * blockDim.x + threadIdx.x;
    if (i >= n8) return;
    const float4* ip = (const float4*)in + (size_t)i * 2;
    float4 v0 = ip[0], v1 = ip[1];
    uint4 o;
    __half2* h = (__half2*)&o;
    h[0] = __floats2half2_rn(v0.x, v0.y);
    h[1] = __floats2half2_rn(v0.z, v0.w);
    h[2] = __floats2half2_rn(v1.x, v1.y);
    h[3] = __floats2half2_rn(v1.z, v1.w);
    ((uint4*)out)[i] = o;
}

// ---------------------------------------------------------------------------
// GEMM, proven mainloop (CTA 128 M x 128 B-rows x 64 K, 4 warps 2x2, warp
// tile 64x64, 2 CTAs/SM, 3-stage ring, cross-stage fragment prefetch).
// L2-aware rasterization — groups of RASTER_G M-tiles swept across N
// (M fastest within group) so a CTA wave's A+B working set fits in L2.
//
// FUSED=1: B rows 0..63 = w1 tile, rows 64..127 = w2 tile (same 64 cols);
//          epilogue h = half(silu(acc_w1)*acc_w2), 64-wide fp16 tile.
// FUSED=0: plain C[M,N] = A@B^T, fp32 out (down-projection).
// ---------------------------------------------------------------------------
#define BM 128
#define BK 64
#define STG_A (BM * BK * 2)              // 16 KB
#define STG_BYTES ((BM + 128) * BK * 2)  // 32 KB
#define NSTAGE 3
#define SMEM_TOTAL (NSTAGE * STG_BYTES)  // 96 KB per CTA
#define RASTER_G 16

__device__ __forceinline__ void cp_async16(uint32_t dst, const void* src) {
    asm volatile("cp.async.cg.shared.global [%0], [%1], 16;\n" ::"r"(dst), "l"(src));
}

template <int FUSED>
__global__ void __launch_bounds__(128, 2) gemm_kernel(
    const __half* __restrict__ A, const __half* __restrict__ B1,
    const __half* __restrict__ B2, void* __restrict__ Cout,
    int M, int Nout, int K) {
    extern __shared__ __align__(128) char smem_raw[];
    uint32_t smem_base = (uint32_t)__cvta_generic_to_shared(smem_raw);

    int tid  = threadIdx.x;
    int lane = tid & 31;
    int warp = tid >> 5;
    int wrow = warp >> 1;  // 0..1 -> 64 rows each
    int wcol = warp & 1;   // 0..1

    // ---- L2-aware rasterization (M-tiles fastest within groups of RASTER_G)
    int tiles_n = gridDim.x;
    int linear = blockIdx.y * tiles_n + blockIdx.x;
    int gsz = RASTER_G * tiles_n;
    int grp = linear / gsz;
    int rem = linear - grp * gsz;
    int m_idx = grp * RASTER_G + (rem % RASTER_G);
    int n_idx = rem / RASTER_G;

    long bm0 = (long)m_idx * BM;
    long bn0 = (long)n_idx * (FUSED ? 64 : 128);

    const __half* Ablk  = A + bm0 * K;
    const __half* B1blk = B1 + bn0 * K;
    const __half* B2blk = FUSED ? (B2 + bn0 * K) : nullptr;

    int KT = K / BK;

    auto load_stage = [&](int kt, int s) {
        uint32_t sa = smem_base + s * STG_BYTES;
        uint32_t sbb = sa + STG_A;
        long koff = (long)kt * BK;
#pragma unroll
        for (int i = 0; i < 8; i++) {
            int e = i * 128 + tid;
            int row = e >> 3;
            int chunk = e & 7;
            uint32_t dst = sa + row * 128 + ((chunk * 16) ^ ((row & 7) * 16));
            cp_async16(dst, Ablk + (long)row * K + koff + chunk * 8);
        }
#pragma unroll
        for (int i = 0; i < 8; i++) {
            int e = i * 128 + tid;
            int row = e >> 3;
            int chunk = e & 7;
            uint32_t dst = sbb + row * 128 + ((chunk * 16) ^ ((row & 7) * 16));
            const __half* src;
            if (FUSED)
                src = (row < 64) ? (B1blk + (long)row * K + koff + chunk * 8)
                                 : (B2blk + (long)(row - 64) * K + koff + chunk * 8);
            else
                src = B1blk + (long)row * K + koff + chunk * 8;
            cp_async16(dst, src);
        }
        asm volatile("cp.async.commit_group;\n");
    };

    float acc[4][8][4];
#pragma unroll
    for (int mt = 0; mt < 4; mt++)
#pragma unroll
        for (int nt = 0; nt < 8; nt++)
#pragma unroll
            for (int r = 0; r < 4; r++) acc[mt][nt][r] = 0.f;

    // ---- Hoisted ldmatrix addressing (XOR field decomposition) ----
    const int a_r  = lane & 15;
    const int a_ch = (lane >> 4) * 16;
    const int swzA = (a_r & 7) * 16;
    const uint32_t qA = (uint32_t)(swzA & 96);
    uint32_t aBase[4];
#pragma unroll
    for (int mt = 0; mt < 4; mt++)
        aBase[mt] = (uint32_t)((wrow * 64 + mt * 16 + a_r) * 128 +
                               (a_ch ^ (swzA & 16)));
    const int b_r  = ((lane >> 4) << 3) + (lane & 7);
    const int b_ch = ((lane >> 3) & 1) * 16;
    const int swzB = (lane & 7) * 16;
    const uint32_t qB = (uint32_t)(swzB & 96);
    uint32_t bBase[4];
#pragma unroll
    for (int p = 0; p < 4; p++) {
        int brow;
        if (FUSED)
            brow = (p < 2) ? (wcol * 32 + p * 16 + b_r)
                           : (64 + wcol * 32 + (p - 2) * 16 + b_r);
        else
            brow = wcol * 64 + p * 16 + b_r;
        bBase[p] = (uint32_t)(STG_A + brow * 128 + (b_ch ^ (swzB & 16)));
    }

    uint32_t a_frag[2][4][4];
    uint32_t b_frag[2][8][2];

    auto load_frags = [&](uint32_t st, int k16, int buf) {
        uint32_t xa = ((uint32_t)(k16 * 32)) ^ qA;
        uint32_t xb = ((uint32_t)(k16 * 32)) ^ qB;
#pragma unroll
        for (int mt = 0; mt < 4; mt++) {
            uint32_t addr = st + aBase[mt] + xa;
            asm volatile(
                "ldmatrix.sync.aligned.m8n8.x4.shared.b16 {%0,%1,%2,%3}, [%4];"
                : "=r"(a_frag[buf][mt][0]), "=r"(a_frag[buf][mt][1]),
                  "=r"(a_frag[buf][mt][2]), "=r"(a_frag[buf][mt][3])
                : "r"(addr));
        }
#pragma unroll
        for (int p = 0; p < 4; p++) {
            uint32_t addr = st + bBase[p] + xb;
            asm volatile(
                "ldmatrix.sync.aligned.m8n8.x4.shared.b16 {%0,%1,%2,%3}, [%4];"
                : "=r"(b_frag[buf][2 * p][0]), "=r"(b_frag[buf][2 * p][1]),
                  "=r"(b_frag[buf][2 * p + 1][0]), "=r"(b_frag[buf][2 * p + 1][1])
                : "r"(addr));
        }
    };

    auto do_mmas = [&](int buf) {
#pragma unroll
        for (int mt = 0; mt < 4; mt++)
#pragma unroll
            for (int nt = 0; nt < 8; nt++) {
                asm volatile(
                    "mma.sync.aligned.m16n8k16.row.col.f32.f16.f16.f32 "
                    "{%0,%1,%2,%3}, {%4,%5,%6,%7}, {%8,%9}, {%0,%1,%2,%3};"
                    : "+f"(acc[mt][nt][0]), "+f"(acc[mt][nt][1]),
                      "+f"(acc[mt][nt][2]), "+f"(acc[mt][nt][3])
                    : "r"(a_frag[buf][mt][0]), "r"(a_frag[buf][mt][1]),
                      "r"(a_frag[buf][mt][2]), "r"(a_frag[buf][mt][3]),
                      "r"(b_frag[buf][nt][0]), "r"(b_frag[buf][nt][1]));
            }
    };

    // Prologue
    load_stage(0, 0);
    load_stage(1, 1);
    asm volatile("cp.async.wait_group 1;\n");
    __syncthreads();
    load_frags(smem_base, 0, 0);

    int sc = 0, sl = 2;
    int buf = 0;
    for (int kt = 0; kt < KT; kt++) {
        __syncthreads();

        if (kt + 2 < KT) load_stage(kt + 2, sl);
        else asm volatile("cp.async.commit_group;\n");

        asm volatile("cp.async.wait_group 1;\n");
        __syncthreads();

        uint32_t st = smem_base + sc * STG_BYTES;
        int sn = sc + 1 == NSTAGE ? 0 : sc + 1;
        uint32_t st_next = (kt + 1 < KT) ? smem_base + sn * STG_BYTES : st;
        sc = sn;
        sl = (sl + 1 == NSTAGE) ? 0 : sl + 1;

#pragma unroll
        for (int k16 = 0; k16 < BK / 16; k16++) {
            if (k16 + 1 < BK / 16)
                load_frags(st, k16 + 1, buf ^ 1);
            else
                load_frags(st_next, 0, buf ^ 1);
            do_mmas(buf);
            buf ^= 1;
        }
    }

    // Epilogue
    if (FUSED) {
#pragma unroll
        for (int mt = 0; mt < 4; mt++) {
#pragma unroll
            for (int nt = 0; nt < 4; nt++) {
                long r0 = bm0 + wrow * 64 + mt * 16 + (lane >> 2);
                long c0 = bn0 + wcol * 32 + nt * 8 + (lane & 3) * 2;
                float g0 = acc[mt][nt][0], g1 = acc[mt][nt][1];
                float g2 = acc[mt][nt][2], g3 = acc[mt][nt][3];
                float u0 = acc[mt][nt + 4][0], u1 = acc[mt][nt + 4][1];
                float u2 = acc[mt][nt + 4][2], u3 = acc[mt][nt + 4][3];
                float h0 = g0 / (1.f + __expf(-g0)) * u0;
                float h1 = g1 / (1.f + __expf(-g1)) * u1;
                float h2 = g2 / (1.f + __expf(-g2)) * u2;
                float h3 = g3 / (1.f + __expf(-g3)) * u3;
                __half* C = (__half*)Cout;
                *(__half2*)(C + r0 * Nout + c0)       = __floats2half2_rn(h0, h1);
                *(__half2*)(C + (r0 + 8) * Nout + c0) = __floats2half2_rn(h2, h3);
            }
        }
    } else {
#pragma unroll
        for (int mt = 0; mt < 4; mt++) {
#pragma unroll
            for (int nt = 0; nt < 8; nt++) {
                long r0 = bm0 + wrow * 64 + mt * 16 + (lane >> 2);
                long c0 = bn0 + wcol * 64 + nt * 8 + (lane & 3) * 2;
                float* C = (float*)Cout;
                *(float2*)(C + r0 * Nout + c0) =
                    make_float2(acc[mt][nt][0], acc[mt][nt][1]);
                *(float2*)(C + (r0 + 8) * Nout + c0) =
                    make_float2(acc[mt][nt][2], acc[mt][nt][3]);
            }
        }
    }
}

// ---------------------------------------------------------------------------
// Launch. Fused up-proj at launch index 3 (the ncu-profiled slot).
// ---------------------------------------------------------------------------
extern "C" void kernel_launch(void* const* d_in, const int* in_sizes, int n_in,
                              void* d_out, int out_size) {
    const float* x = (const float*)d_in[0];
    const int* w1c = (const int*)d_in[1];
    const float* w1s = (const float*)d_in[2];
    const int* w2c = (const int*)d_in[3];
    const float* w2s = (const float*)d_in[4];
    const int* w3c = (const int*)d_in[5];
    const float* w3s = (const float*)d_in[6];

    int T = in_sizes[0] / D_DIM;  // 8192

    __half *w1h, *w2h, *w3h, *xh, *hbuf;
    cudaGetSymbolAddress((void**)&w1h, g_w1);
    cudaGetSymbolAddress((void**)&w2h, g_w2);
    cudaGetSymbolAddress((void**)&w3h, g_w3);
    cudaGetSymbolAddress((void**)&xh, g_x);
    cudaGetSymbolAddress((void**)&hbuf, g_h);

    cudaFuncSetAttribute(gemm_kernel<1>, cudaFuncAttributeMaxDynamicSharedMemorySize, SMEM_TOTAL);
    cudaFuncSetAttribute(gemm_kernel<0>, cudaFuncAttributeMaxDynamicSharedMemorySize, SMEM_TOTAL);

    int nW16 = (H_DIM * D_DIM) / 16;
    int nX8 = (T * D_DIM) / 8;
    dim3 gf(H_DIM / 64, T / BM);   // fused up-proj: 172 x 64
    dim3 g2(D_DIM / 128, T / BM);  // down-proj: 32 x 64

    // idx 0: w1 dequant
    dequant_nf4_kernel<<<(nW16 + 255) / 256, 256>>>(w1c, w1s, w1h, nW16);
    // idx 1: w2 dequant
    dequant_nf4_kernel<<<(nW16 + 255) / 256, 256>>>(w2c, w2s, w2h, nW16);
    // idx 2: x -> fp16
    f32_to_f16_kernel<<<(nX8 + 255) / 256, 256>>>(x, xh, nX8);
    // idx 3 (ncu-profiled slot): h = silu(x@w1^T) * (x@w2^T)  [fused, fp16]
    gemm_kernel<1><<<gf, 128, SMEM_TOTAL>>>(xh, w1h, w2h, hbuf, T, H_DIM, D_DIM);
    // idx 4: w3 dequant
    dequant_nf4_kernel<<<(nW16 + 255) / 256, 256>>>(w3c, w3s, w3h, nW16);
    // idx 5: out = h @ w3^T (fp32)
    gemm_kernel<0><<<g2, 128, SMEM_TOTAL>>>(hbuf, w3h, nullptr, d_out, T, D_DIM, H_DIM);
}

// round 16
// speedup vs baseline: 1.0293x; 1.0051x over previous
#include <cuda_runtime.h>
#include <cuda_fp16.h>
#include <cstdint>

// Problem dims (fixed by the dataset)
#define D_DIM 4096
#define H_DIM 11008
#define T_MAX 8192

__device__ __constant__ float c_nf4[16] = {
    -1.0f, -0.6961928009986877f, -0.5250730514526367f, -0.39491748809814453f,
    -0.28444138169288635f, -0.18477343022823334f, -0.09105003625154495f, 0.0f,
    0.07958029955625534f, 0.16093020141124725f, 0.24611230194568634f,
    0.33791524171829224f, 0.44070982933044434f, 0.5626170039176941f,
    0.7229568362236023f, 1.0f};

// Scratch (static __device__ arrays: allocation-guard safe)
__device__ __align__(256) __half g_w1[(size_t)H_DIM * D_DIM];
__device__ __align__(256) __half g_w2[(size_t)H_DIM * D_DIM];
__device__ __align__(256) __half g_w3[(size_t)D_DIM * H_DIM];
__device__ __align__(256) __half g_x [(size_t)T_MAX * D_DIM];
__device__ __align__(256) __half g_h [(size_t)T_MAX * H_DIM];

// ---------------------------------------------------------------------------
// Elementwise prep — widened to 32 codes/thread (MLP~8), one scaler per
// half-block pair (i>>1: 32 codes = exactly half a 64-elem scaler block).
// Arithmetic identical to prior rounds (bit-exact outputs).
// ---------------------------------------------------------------------------
__device__ __forceinline__ void dq16v(const int4* __restrict__ cp, float s,
                                      uint4* __restrict__ op) {
    int4 c0 = cp[0], c1 = cp[1], c2 = cp[2], c3 = cp[3];
    uint4 o0, o1;
    __half2* h = (__half2*)&o0;
    h[0] = __floats2half2_rn(c_nf4[c0.x & 15] * s, c_nf4[c0.y & 15] * s);
    h[1] = __floats2half2_rn(c_nf4[c0.z & 15] * s, c_nf4[c0.w & 15] * s);
    h[2] = __floats2half2_rn(c_nf4[c1.x & 15] * s, c_nf4[c1.y & 15] * s);
    h[3] = __floats2half2_rn(c_nf4[c1.z & 15] * s, c_nf4[c1.w & 15] * s);
    __half2* g = (__half2*)&o1;
    g[0] = __floats2half2_rn(c_nf4[c2.x & 15] * s, c_nf4[c2.y & 15] * s);
    g[1] = __floats2half2_rn(c_nf4[c2.z & 15] * s, c_nf4[c2.w & 15] * s);
    g[2] = __floats2half2_rn(c_nf4[c3.x & 15] * s, c_nf4[c3.y & 15] * s);
    g[3] = __floats2half2_rn(c_nf4[c3.z & 15] * s, c_nf4[c3.w & 15] * s);
    op[0] = o0;
    op[1] = o1;
}

__global__ void dequant_nf4_kernel(const int* __restrict__ codes,
                                   const float* __restrict__ scalers,
                                   __half* __restrict__ out, int n32) {
    int i = blockIdx.x * blockDim.x + threadIdx.x;
    if (i >= n32) return;
    const int4* cp = (const int4*)codes + (size_t)i * 8;
    uint4* op = (uint4*)out + (size_t)i * 4;
    float s = __ldg(&scalers[i >> 1]);  // 32 codes/thread; 64-elem blocks
    dq16v(cp, s, op);
    dq16v(cp + 4, s, op + 2);
}

__global__ void f32_to_f16_kernel(const float* __restrict__ in,
                                  __half* __restrict__ out, int n16) {
    int i = blockIdx.x * blockDim.x + threadIdx.x;
    if (i >= n16) return;
    const float4* ip = (const float4*)in + (size_t)i * 4;
    float4 v0 = ip[0], v1 = ip[1], v2 = ip[2], v3 = ip[3];
    uint4 o0, o1;
    __half2* h = (__half2*)&o0;
    h[0] = __floats2half2_rn(v0.x, v0.y);
    h[1] = __floats2half2_rn(v0.z, v0.w);
    h[2] = __floats2half2_rn(v1.x, v1.y);
    h[3] = __floats2half2_rn(v1.z, v1.w);
    __half2* g = (__half2*)&o1;
    g[0] = __floats2half2_rn(v2.x, v2.y);
    g[1] = __floats2half2_rn(v2.z, v2.w);
    g[2] = __floats2half2_rn(v3.x, v3.y);
    g[3] = __floats2half2_rn(v3.z, v3.w);
    uint4* op = (uint4*)out + (size_t)i * 2;
    op[0] = o0;
    op[1] = o1;
}

// ---------------------------------------------------------------------------
// GEMM, proven mainloop (CTA 128 M x 128 B-rows x 64 K, 4 warps 2x2, warp
// tile 64x64, 2 CTAs/SM, 3-stage ring, cross-stage fragment prefetch).
// L2-aware rasterization — groups of RASTER_G M-tiles swept across N.
// (Byte-for-byte the round-12 best configuration.)
//
// FUSED=1: B rows 0..63 = w1 tile, rows 64..127 = w2 tile (same 64 cols);
//          epilogue h = half(silu(acc_w1)*acc_w2), 64-wide fp16 tile.
// FUSED=0: plain C[M,N] = A@B^T, fp32 out (down-projection).
// ---------------------------------------------------------------------------
#define BM 128
#define BK 64
#define STG_A (BM * BK * 2)              // 16 KB
#define STG_BYTES ((BM + 128) * BK * 2)  // 32 KB
#define NSTAGE 3
#define SMEM_TOTAL (NSTAGE * STG_BYTES)  // 96 KB per CTA
#define RASTER_G 16

__device__ __forceinline__ void cp_async16(uint32_t dst, const void* src) {
    asm volatile("cp.async.cg.shared.global [%0], [%1], 16;\n" ::"r"(dst), "l"(src));
}

template <int FUSED>
__global__ void __launch_bounds__(128, 2) gemm_kernel(
    const __half* __restrict__ A, const __half* __restrict__ B1,
    const __half* __restrict__ B2, void* __restrict__ Cout,
    int M, int Nout, int K) {
    extern __shared__ __align__(128) char smem_raw[];
    uint32_t smem_base = (uint32_t)__cvta_generic_to_shared(smem_raw);

    int tid  = threadIdx.x;
    int lane = tid & 31;
    int warp = tid >> 5;
    int wrow = warp >> 1;  // 0..1 -> 64 rows each
    int wcol = warp & 1;   // 0..1

    // ---- L2-aware rasterization (M-tiles fastest within groups of RASTER_G)
    int tiles_n = gridDim.x;
    int linear = blockIdx.y * tiles_n + blockIdx.x;
    int gsz = RASTER_G * tiles_n;
    int grp = linear / gsz;
    int rem = linear - grp * gsz;
    int m_idx = grp * RASTER_G + (rem % RASTER_G);
    int n_idx = rem / RASTER_G;

    long bm0 = (long)m_idx * BM;
    long bn0 = (long)n_idx * (FUSED ? 64 : 128);

    const __half* Ablk  = A + bm0 * K;
    const __half* B1blk = B1 + bn0 * K;
    const __half* B2blk = FUSED ? (B2 + bn0 * K) : nullptr;

    int KT = K / BK;

    auto load_stage = [&](int kt, int s) {
        uint32_t sa = smem_base + s * STG_BYTES;
        uint32_t sbb = sa + STG_A;
        long koff = (long)kt * BK;
#pragma unroll
        for (int i = 0; i < 8; i++) {
            int e = i * 128 + tid;
            int row = e >> 3;
            int chunk = e & 7;
            uint32_t dst = sa + row * 128 + ((chunk * 16) ^ ((row & 7) * 16));
            cp_async16(dst, Ablk + (long)row * K + koff + chunk * 8);
        }
#pragma unroll
        for (int i = 0; i < 8; i++) {
            int e = i * 128 + tid;
            int row = e >> 3;
            int chunk = e & 7;
            uint32_t dst = sbb + row * 128 + ((chunk * 16) ^ ((row & 7) * 16));
            const __half* src;
            if (FUSED)
                src = (row < 64) ? (B1blk + (long)row * K + koff + chunk * 8)
                                 : (B2blk + (long)(row - 64) * K + koff + chunk * 8);
            else
                src = B1blk + (long)row * K + koff + chunk * 8;
            cp_async16(dst, src);
        }
        asm volatile("cp.async.commit_group;\n");
    };

    float acc[4][8][4];
#pragma unroll
    for (int mt = 0; mt < 4; mt++)
#pragma unroll
        for (int nt = 0; nt < 8; nt++)
#pragma unroll
            for (int r = 0; r < 4; r++) acc[mt][nt][r] = 0.f;

    // ---- Hoisted ldmatrix addressing (XOR field decomposition) ----
    const int a_r  = lane & 15;
    const int a_ch = (lane >> 4) * 16;
    const int swzA = (a_r & 7) * 16;
    const uint32_t qA = (uint32_t)(swzA & 96);
    uint32_t aBase[4];
#pragma unroll
    for (int mt = 0; mt < 4; mt++)
        aBase[mt] = (uint32_t)((wrow * 64 + mt * 16 + a_r) * 128 +
                               (a_ch ^ (swzA & 16)));
    const int b_r  = ((lane >> 4) << 3) + (lane & 7);
    const int b_ch = ((lane >> 3) & 1) * 16;
    const int swzB = (lane & 7) * 16;
    const uint32_t qB = (uint32_t)(swzB & 96);
    uint32_t bBase[4];
#pragma unroll
    for (int p = 0; p < 4; p++) {
        int brow;
        if (FUSED)
            brow = (p < 2) ? (wcol * 32 + p * 16 + b_r)
                           : (64 + wcol * 32 + (p - 2) * 16 + b_r);
        else
            brow = wcol * 64 + p * 16 + b_r;
        bBase[p] = (uint32_t)(STG_A + brow * 128 + (b_ch ^ (swzB & 16)));
    }

    uint32_t a_frag[2][4][4];
    uint32_t b_frag[2][8][2];

    auto load_frags = [&](uint32_t st, int k16, int buf) {
        uint32_t xa = ((uint32_t)(k16 * 32)) ^ qA;
        uint32_t xb = ((uint32_t)(k16 * 32)) ^ qB;
#pragma unroll
        for (int mt = 0; mt < 4; mt++) {
            uint32_t addr = st + aBase[mt] + xa;
            asm volatile(
                "ldmatrix.sync.aligned.m8n8.x4.shared.b16 {%0,%1,%2,%3}, [%4];"
                : "=r"(a_frag[buf][mt][0]), "=r"(a_frag[buf][mt][1]),
                  "=r"(a_frag[buf][mt][2]), "=r"(a_frag[buf][mt][3])
                : "r"(addr));
        }
#pragma unroll
        for (int p = 0; p < 4; p++) {
            uint32_t addr = st + bBase[p] + xb;
            asm volatile(
                "ldmatrix.sync.aligned.m8n8.x4.shared.b16 {%0,%1,%2,%3}, [%4];"
                : "=r"(b_frag[buf][2 * p][0]), "=r"(b_frag[buf][2 * p][1]),
                  "=r"(b_frag[buf][2 * p + 1][0]), "=r"(b_frag[buf][2 * p + 1][1])
                : "r"(addr));
        }
    };

    auto do_mmas = [&](int buf) {
#pragma unroll
        for (int mt = 0; mt < 4; mt++)
#pragma unroll
            for (int nt = 0; nt < 8; nt++) {
                asm volatile(
                    "mma.sync.aligned.m16n8k16.row.col.f32.f16.f16.f32 "
                    "{%0,%1,%2,%3}, {%4,%5,%6,%7}, {%8,%9}, {%0,%1,%2,%3};"
                    : "+f"(acc[mt][nt][0]), "+f"(acc[mt][nt][1]),
                      "+f"(acc[mt][nt][2]), "+f"(acc[mt][nt][3])
                    : "r"(a_frag[buf][mt][0]), "r"(a_frag[buf][mt][1]),
                      "r"(a_frag[buf][mt][2]), "r"(a_frag[buf][mt][3]),
                      "r"(b_frag[buf][nt][0]), "r"(b_frag[buf][nt][1]));
            }
    };

    // Prologue
    load_stage(0, 0);
    load_stage(1, 1);
    asm volatile("cp.async.wait_group 1;\n");
    __syncthreads();
    load_frags(smem_base, 0, 0);

    int sc = 0, sl = 2;
    int buf = 0;
    for (int kt = 0; kt < KT; kt++) {
        __syncthreads();

        if (kt + 2 < KT) load_stage(kt + 2, sl);
        else asm volatile("cp.async.commit_group;\n");

        asm volatile("cp.async.wait_group 1;\n");
        __syncthreads();

        uint32_t st = smem_base + sc * STG_BYTES;
        int sn = sc + 1 == NSTAGE ? 0 : sc + 1;
        uint32_t st_next = (kt + 1 < KT) ? smem_base + sn * STG_BYTES : st;
        sc = sn;
        sl = (sl + 1 == NSTAGE) ? 0 : sl + 1;

#pragma unroll
        for (int k16 = 0; k16 < BK / 16; k16++) {
            if (k16 + 1 < BK / 16)
                load_frags(st, k16 + 1, buf ^ 1);
            else
                load_frags(st_next, 0, buf ^ 1);
            do_mmas(buf);
            buf ^= 1;
        }
    }

    // Epilogue
    if (FUSED) {
#pragma unroll
        for (int mt = 0; mt < 4; mt++) {
#pragma unroll
            for (int nt = 0; nt < 4; nt++) {
                long r0 = bm0 + wrow * 64 + mt * 16 + (lane >> 2);
                long c0 = bn0 + wcol * 32 + nt * 8 + (lane & 3) * 2;
                float g0 = acc[mt][nt][0], g1 = acc[mt][nt][1];
                float g2 = acc[mt][nt][2], g3 = acc[mt][nt][3];
                float u0 = acc[mt][nt + 4][0], u1 = acc[mt][nt + 4][1];
                float u2 = acc[mt][nt + 4][2], u3 = acc[mt][nt + 4][3];
                float h0 = g0 / (1.f + __expf(-g0)) * u0;
                float h1 = g1 / (1.f + __expf(-g1)) * u1;
                float h2 = g2 / (1.f + __expf(-g2)) * u2;
                float h3 = g3 / (1.f + __expf(-g3)) * u3;
                __half* C = (__half*)Cout;
                *(__half2*)(C + r0 * Nout + c0)       = __floats2half2_rn(h0, h1);
                *(__half2*)(C + (r0 + 8) * Nout + c0) = __floats2half2_rn(h2, h3);
            }
        }
    } else {
#pragma unroll
        for (int mt = 0; mt < 4; mt++) {
#pragma unroll
            for (int nt = 0; nt < 8; nt++) {
                long r0 = bm0 + wrow * 64 + mt * 16 + (lane >> 2);
                long c0 = bn0 + wcol * 64 + nt * 8 + (lane & 3) * 2;
                float* C = (float*)Cout;
                *(float2*)(C + r0 * Nout + c0) =
                    make_float2(acc[mt][nt][0], acc[mt][nt][1]);
                *(float2*)(C + (r0 + 8) * Nout + c0) =
                    make_float2(acc[mt][nt][2], acc[mt][nt][3]);
            }
        }
    }
}

// ---------------------------------------------------------------------------
// Launch. Fused up-proj at launch index 3 (the ncu-profiled slot).
// ---------------------------------------------------------------------------
extern "C" void kernel_launch(void* const* d_in, const int* in_sizes, int n_in,
                              void* d_out, int out_size) {
    const float* x = (const float*)d_in[0];
    const int* w1c = (const int*)d_in[1];
    const float* w1s = (const float*)d_in[2];
    const int* w2c = (const int*)d_in[3];
    const float* w2s = (const float*)d_in[4];
    const int* w3c = (const int*)d_in[5];
    const float* w3s = (const float*)d_in[6];

    int T = in_sizes[0] / D_DIM;  // 8192

    __half *w1h, *w2h, *w3h, *xh, *hbuf;
    cudaGetSymbolAddress((void**)&w1h, g_w1);
    cudaGetSymbolAddress((void**)&w2h, g_w2);
    cudaGetSymbolAddress((void**)&w3h, g_w3);
    cudaGetSymbolAddress((void**)&xh, g_x);
    cudaGetSymbolAddress((void**)&hbuf, g_h);

    cudaFuncSetAttribute(gemm_kernel<1>, cudaFuncAttributeMaxDynamicSharedMemorySize, SMEM_TOTAL);
    cudaFuncSetAttribute(gemm_kernel<0>, cudaFuncAttributeMaxDynamicSharedMemorySize, SMEM_TOTAL);

    int nW32 = (H_DIM * D_DIM) / 32;  // 32 codes per thread
    int nX16 = (T * D_DIM) / 16;      // 16 floats per thread
    dim3 gf(H_DIM / 64, T / BM);   // fused up-proj: 172 x 64
    dim3 g2(D_DIM / 128, T / BM);  // down-proj: 32 x 64

    // idx 0: w1 dequant
    dequant_nf4_kernel<<<(nW32 + 255) / 256, 256>>>(w1c, w1s, w1h, nW32);
    // idx 1: w2 dequant
    dequant_nf4_kernel<<<(nW32 + 255) / 256, 256>>>(w2c, w2s, w2h, nW32);
    // idx 2: x -> fp16
    f32_to_f16_kernel<<<(nX16 + 255) / 256, 256>>>(x, xh, nX16);
    // idx 3 (ncu-profiled slot): h = silu(x@w1^T) * (x@w2^T)  [fused, fp16]
    gemm_kernel<1><<<gf, 128, SMEM_TOTAL>>>(xh, w1h, w2h, hbuf, T, H_DIM, D_DIM);
    // idx 4: w3 dequant
    dequant_nf4_kernel<<<(nW32 + 255) / 256, 256>>>(w3c, w3s, w3h, nW32);
    // idx 5: out = h @ w3^T (fp32)
    gemm_kernel<0><<<g2, 128, SMEM_TOTAL>>>(hbuf, w3h, nullptr, d_out, T, D_DIM, H_DIM);
}